// round 13
// baseline (speedup 1.0000x reference)
#include <cuda_runtime.h>
#include <cuda_fp16.h>
#include <math.h>
#include <stdint.h>

// ---------------------------------------------------------------------------
// GCN: out = relu(BN(conv3x3( D^-1/2 (A+I) D^-1/2 x ))), A = ind^T per batch
// b=8, c=256, n=1024 (32x32).
// R13 = R12 (512-thread GEMM CTAs, 16 warps, 32x32 tile/warp, full-chunk
// fragment preload) with the MODE-2 epilogue extent bug fixed:
// 4 parts/channel x 32 floats (was erroneously 4 x 64 -> OOB write in g_y).
// ---------------------------------------------------------------------------

#define BATCH 8
#define C     256
#define NPOS  1024
#define PADN  1156       // 34*34 zero-padded spatial
#define K2    2304       // 9*256 conv reduction

// ------------------------- device scratch ----------------------------------
__device__ __align__(16) float g_part[BATCH*NPOS*16];    // [b][i][jt] coalesced
__device__ __align__(16) float g_d[BATCH*NPOS];
__device__ __align__(16) __half g_iT[BATCH*NPOS*NPOS];   // (A+I)[i][j] fp16
__device__ __align__(16) __half g_xs[BATCH*C*NPOS];      // x*d[j], [c][j]
__device__ __align__(16) __half g_ip[BATCH*PADN*C];      // inter_pad [ppos][ci]
__device__ __align__(16) __half g_w2[C*K2];              // [co][tap*256+ci]
__device__ __align__(16) float g_y[BATCH*C*NPOS];        // conv out [b][co][pos]
__device__ __align__(16) float g_ps[C*64], g_pq[C*64];   // [co][slot]

// ------------------------- ptx helpers -------------------------------------
__device__ __forceinline__ uint32_t smem_u32(const void* p) {
    uint32_t a;
    asm("{ .reg .u64 t; cvta.to.shared.u64 t, %1; cvt.u32.u64 %0, t; }" : "=r"(a) : "l"(p));
    return a;
}
__device__ __forceinline__ void cp16(uint32_t dst, const void* src) {
    asm volatile("cp.async.cg.shared.global [%0], [%1], 16;" :: "r"(dst), "l"(src));
}
#define CP_COMMIT() asm volatile("cp.async.commit_group;" ::: "memory")
#define CP_WAIT(n)  asm volatile("cp.async.wait_group %0;" :: "n"(n) : "memory")

__device__ __forceinline__ void ldsm4(uint32_t* d, uint32_t addr) {
    asm volatile("ldmatrix.sync.aligned.m8n8.x4.shared.b16 {%0,%1,%2,%3}, [%4];"
        : "=r"(d[0]), "=r"(d[1]), "=r"(d[2]), "=r"(d[3]) : "r"(addr));
}
__device__ __forceinline__ void mma16816h(float* c, const uint32_t* a, const uint32_t* b) {
    asm volatile("mma.sync.aligned.m16n8k16.row.col.f32.f16.f16.f32 "
        "{%0,%1,%2,%3}, {%4,%5,%6,%7}, {%8,%9}, {%0,%1,%2,%3};"
        : "+f"(c[0]), "+f"(c[1]), "+f"(c[2]), "+f"(c[3])
        : "r"(a[0]), "r"(a[1]), "r"(a[2]), "r"(a[3]), "r"(b[0]), "r"(b[1]));
}

// ------------------------- prep kernels ------------------------------------
// 64x64 tile transpose ind -> fp16 (A+I); fused degree partials (pre-identity).
__global__ void __launch_bounds__(256) tsplit_deg_kernel(const float* __restrict__ ind) {
    __shared__ float t[64][65];
    int b = blockIdx.z;
    int i0 = blockIdx.x * 64, j0 = blockIdx.y * 64;
    int tid = threadIdx.x;

    {   // load 64 rows (j) x 64 cols (i), float4
        int r = tid >> 2, q = tid & 3;
        const float* src = ind + ((size_t)(b * NPOS + j0 + r)) * NPOS + i0;
        #pragma unroll
        for (int k = 0; k < 4; ++k) {
            float4 v = *(const float4*)(src + q * 4 + k * 16);
            t[r][q * 4 + k * 16]     = v.x;
            t[r][q * 4 + k * 16 + 1] = v.y;
            t[r][q * 4 + k * 16 + 2] = v.z;
            t[r][q * 4 + k * 16 + 3] = v.w;
        }
    }
    __syncthreads();

    int jh = tid & 31;                 // lane: half2 j index
    int wi = tid >> 5;                 // warp -> i row group
    #pragma unroll
    for (int iter = 0; iter < 8; ++iter) {
        int il = wi + iter * 8;
        int i = i0 + il;
        float r0 = t[2 * jh][il];
        float r1 = t[2 * jh + 1][il];
        float s = r0 + r1;             // degree BEFORE identity
        float v0 = r0 + ((i == j0 + 2 * jh)     ? 1.f : 0.f);
        float v1 = r1 + ((i == j0 + 2 * jh + 1) ? 1.f : 0.f);
        *(__half2*)(g_iT + ((size_t)(b * NPOS + i)) * NPOS + j0 + 2 * jh) =
            __floats2half2_rn(v0, v1);
        #pragma unroll
        for (int off = 16; off > 0; off >>= 1)
            s += __shfl_xor_sync(0xffffffffu, s, off);
        if (jh == 0)
            g_part[((size_t)(b * NPOS + i)) * 16 + blockIdx.y] = s;
    }
}

// combo: [0,2304) w->fp16 relayout | [2304,2436) pad border | [2436,2468) deg
__global__ void combo_kernel(const float* __restrict__ w) {
    int blk = blockIdx.x, tid = threadIdx.x;
    if (blk < 2304) {
        int o = blk * 256 + tid;              // < 256*2304
        int co = o / K2;
        int r = o - co * K2;
        int tap = r >> 8, ci = r & 255;
        g_w2[o] = __float2half(w[(size_t)(co * C + ci) * 9 + tap]);
    } else if (blk < 2436) {
        int k = blk - 2304;                   // border row 0..131
        int pp;
        if (k < 34)      pp = k;                              // top row
        else if (k < 68) pp = 33 * 34 + (k - 34);             // bottom row
        else {
            int m = k - 68;
            pp = (1 + (m >> 1)) * 34 + ((m & 1) ? 33 : 0);    // side cols
        }
        int b = tid >> 5, u = tid & 31;       // 8 batches x 32 uint4 = 256B row
        ((uint4*)(g_ip + ((size_t)(b * PADN + pp)) * C))[u] = make_uint4(0, 0, 0, 0);
    } else {
        int gi = (blk - 2436) * 256 + tid;    // (b,i) 0..8191
        const float4* p = (const float4*)(g_part + (size_t)gi * 16);
        float s = 0.f;
        #pragma unroll
        for (int k = 0; k < 4; ++k) {
            float4 v = p[k];
            s += (v.x + v.y) + (v.z + v.w);
        }
        g_d[gi] = sqrtf(1.0f / (s + 1e-8f));
    }
}

// xs[b][c][j] = fp16( x[b][c][j] * d[b][j] )
__global__ void xs_half_kernel(const float* __restrict__ x) {
    size_t idx = (size_t)blockIdx.x * 256 + threadIdx.x;
    int j = (int)(idx & (NPOS - 1));
    int b = (int)(idx >> 18);
    g_xs[idx] = __float2half(x[idx] * g_d[b * NPOS + j]);
}

// ------------------------- fp16 mma GEMM ------------------------------------
// MODE 1: D[pos 128][c 128]  = iT (A) . xs (B),             K=1024 (16 chunks)
// MODE 2: D[pos 128][co 128] = inter_pad shifted (A) . w2,  K=2304 (36 chunks)
// 512 threads, 16 warps in 4x4 grid, 32x32 tile/warp.
// Stage = A|B, each 128x64 fp16 (16KB) -> 32KB/stage, 4-stage ring = 128KB.
static constexpr int SMEM_DYN = 4 * 32768;

template<int MODE>
__global__ void __launch_bounds__(512, 1) gemm_half(const float* __restrict__ conv_b) {
    extern __shared__ char smem[];
    uint32_t sb = smem_u32(smem);
    const int tid = threadIdx.x;
    const int pos0 = blockIdx.x * 128, n0 = blockIdx.y * 128, b = blockIdx.z;
    constexpr int CHUNKS = (MODE == 1) ? 16 : 36;

    auto stage = [&](int c, int p) {
        uint32_t base = sb + p * 32768;
        #pragma unroll
        for (int it = 0; it < 2; ++it) {
            int u = it * 512 + tid;           // 1024 16B-units per tile
            int r = u >> 3, g = u & 7;
            uint32_t sw = (uint32_t)(r * 128 + ((g ^ (r & 7)) * 16));
            const __half *pa, *pb;
            if (MODE == 1) {
                pa = g_iT + ((size_t)(b * NPOS + pos0 + r)) * NPOS + c * 64 + g * 8;
                pb = g_xs + ((size_t)(b * C + n0 + r)) * NPOS + c * 64 + g * 8;
            } else {
                int tap = c >> 2, ci0 = (c & 3) * 64;
                int pos = pos0 + r;
                int pp = ((pos >> 5) + 1) * 34 + (pos & 31) + 1
                         + (tap / 3 - 1) * 34 + (tap % 3 - 1);
                pa = g_ip + ((size_t)(b * PADN + pp)) * C + ci0 + g * 8;
                pb = g_w2 + ((size_t)(n0 + r)) * K2 + c * 64 + g * 8;
            }
            cp16(base + sw, pa);
            cp16(base + 16384 + sw, pb);
        }
    };

    const int l = tid & 31, w = tid >> 5;          // 16 warps
    const int wm = w >> 2, wn = w & 3;             // 4 x 4 warp grid
    const int mbase = wm * 32, nbase = wn * 32;
    const int lr = l & 15;
    const uint32_t arow = (uint32_t)((mbase + lr) * 128);
    const uint32_t brow = (uint32_t)((nbase + lr) * 128);
    uint32_t u16[4];
    #pragma unroll
    for (int kk = 0; kk < 4; ++kk)
        u16[kk] = (uint32_t)(((kk * 2 + (l >> 4)) ^ (l & 7)) * 16);

    float acc[2][4][4];
    #pragma unroll
    for (int i = 0; i < 2; ++i)
        #pragma unroll
        for (int j = 0; j < 4; ++j)
            #pragma unroll
            for (int e = 0; e < 4; ++e) acc[i][j][e] = 0.f;

    stage(0, 0); CP_COMMIT();
    stage(1, 1); CP_COMMIT();
    stage(2, 2); CP_COMMIT();

    for (int c = 0; c < CHUNKS; ++c) {
        CP_WAIT(2);          // chunk c landed
        __syncthreads();     // all warps finished compute(c-1) -> its buffer free
        if (c + 3 < CHUNKS) { stage(c + 3, (c + 3) & 3); CP_COMMIT(); }
        uint32_t bb = sb + (c & 3) * 32768;

        // full-chunk fragment preload: 16 independent ldsm
        uint32_t ah[4][2][4], bh[4][2][4];     // [kk][mi|nb][frag]
        #pragma unroll
        for (int kk = 0; kk < 4; ++kk) {
            #pragma unroll
            for (int mi = 0; mi < 2; ++mi)
                ldsm4(ah[kk][mi], bb + arow + mi * 2048 + u16[kk]);
            #pragma unroll
            for (int nb = 0; nb < 2; ++nb)
                ldsm4(bh[kk][nb], bb + 16384 + brow + nb * 2048 + u16[kk]);
        }
        #pragma unroll
        for (int kk = 0; kk < 4; ++kk)
            #pragma unroll
            for (int mi = 0; mi < 2; ++mi)
                #pragma unroll
                for (int nj = 0; nj < 4; ++nj) {
                    int nb = nj >> 1, s = nj & 1;
                    uint32_t fh[2] = { bh[kk][nb][s], bh[kk][nb][s + 2] };
                    mma16816h(acc[mi][nj], ah[kk][mi], fh);
                }
    }
    __syncthreads();          // ring smem free for epilogue reuse

    // ---------------- epilogue ----------------
    int qr = l >> 2, qc = (l & 3) * 2;
    if (MODE == 1) {
        // stage fp16 tile [pos][ci] in smem, then coalesced 256B row writes
        __half* ips = (__half*)smem;               // [128][136]
        #pragma unroll
        for (int mi = 0; mi < 2; ++mi)
            #pragma unroll
            for (int half = 0; half < 2; ++half) {
                int pl = mbase + mi * 16 + qr + half * 8;
                float di = g_d[b * NPOS + pos0 + pl];
                #pragma unroll
                for (int nj = 0; nj < 4; ++nj) {
                    *(__half2*)(ips + pl * 136 + nbase + nj * 8 + qc) =
                        __floats2half2_rn(di * acc[mi][nj][half * 2],
                                          di * acc[mi][nj][half * 2 + 1]);
                }
            }
        __syncthreads();
        int row = tid >> 2, q4 = tid & 3;         // 128 rows x (4 parts x 4 uint4)
        int pos = pos0 + row;
        int pp = ((pos >> 5) + 1) * 34 + (pos & 31) + 1;
        uint4* dst = (uint4*)(g_ip + ((size_t)(b * PADN + pp)) * C + n0) + q4 * 4;
        const uint4* srcp = (const uint4*)(ips + row * 136) + q4 * 4;
        #pragma unroll
        for (int k = 0; k < 4; ++k) dst[k] = srcp[k];
    } else {
        // stage fp32 tile transposed [co][pos] in smem; stream rows + BN partials
        float* ys = (float*)smem;                  // [128][132]
        #pragma unroll
        for (int mi = 0; mi < 2; ++mi)
            #pragma unroll
            for (int half = 0; half < 2; ++half) {
                int pl = mbase + mi * 16 + qr + half * 8;
                #pragma unroll
                for (int nj = 0; nj < 4; ++nj) {
                    int cl = nbase + nj * 8 + qc;
                    ys[cl * 132 + pl]       = acc[mi][nj][half * 2]     + conv_b[n0 + cl];
                    ys[(cl + 1) * 132 + pl] = acc[mi][nj][half * 2 + 1] + conv_b[n0 + cl + 1];
                }
            }
        __syncthreads();
        int cl = tid >> 2, part = tid & 3;        // 128 channels x 4 parts x 32 floats
        const float4* rowp = (const float4*)(ys + cl * 132 + part * 32);
        float4* dst = (float4*)(g_y + ((size_t)(b * C + n0 + cl)) * NPOS + pos0 + part * 32);
        float s = 0.f, q = 0.f;
        #pragma unroll
        for (int k = 0; k < 8; ++k) {
            float4 v = rowp[k];
            s += (v.x + v.y) + (v.z + v.w);
            q += (v.x * v.x + v.y * v.y) + (v.z * v.z + v.w * v.w);
            dst[k] = v;
        }
        s += __shfl_xor_sync(0xffffffffu, s, 1);
        q += __shfl_xor_sync(0xffffffffu, q, 1);
        s += __shfl_xor_sync(0xffffffffu, s, 2);
        q += __shfl_xor_sync(0xffffffffu, q, 2);
        if (part == 0) {
            int slot = blockIdx.x * 8 + blockIdx.z;     // 0..63
            g_ps[(n0 + cl) * 64 + slot] = s;
            g_pq[(n0 + cl) * 64 + slot] = q;
        }
    }
}

// ------------------------- fused BN stats + apply ---------------------------
// one block = one (b,co) row of g_y (1024 floats = 256 float4)
__global__ void apply_kernel(float* __restrict__ out,
                             const float* __restrict__ gamma,
                             const float* __restrict__ beta) {
    __shared__ float sps[64], spq[64];
    int tid = threadIdx.x;
    int co = blockIdx.x & (C - 1);
    if (tid < 64)       sps[tid] = g_ps[co * 64 + tid];
    else if (tid < 128) spq[tid - 64] = g_pq[co * 64 + tid - 64];
    __syncthreads();
    float s = 0.f, q = 0.f;
    #pragma unroll
    for (int k = 0; k < 64; ++k) { s += sps[k]; q += spq[k]; }
    float mean = s * (1.0f / 8192.0f);
    float var  = q * (1.0f / 8192.0f) - mean * mean;
    float sc = gamma[co] * rsqrtf(var + 1e-5f);
    float sh = beta[co] - mean * sc;

    int i4 = blockIdx.x * 256 + tid;
    float4 v = ((const float4*)g_y)[i4];
    v.x = fmaxf(fmaf(v.x, sc, sh), 0.f);
    v.y = fmaxf(fmaf(v.y, sc, sh), 0.f);
    v.z = fmaxf(fmaf(v.z, sc, sh), 0.f);
    v.w = fmaxf(fmaf(v.w, sc, sh), 0.f);
    ((float4*)out)[i4] = v;
}

// ---------------------------------------------------------------------------
extern "C" void kernel_launch(void* const* d_in, const int* in_sizes, int n_in,
                              void* d_out, int out_size) {
    const float* x      = (const float*)d_in[0];
    const float* ind    = (const float*)d_in[1];
    const float* conv_w = (const float*)d_in[2];
    const float* conv_b = (const float*)d_in[3];
    const float* gamma  = (const float*)d_in[4];
    const float* beta   = (const float*)d_in[5];
    float* out = (float*)d_out;

    cudaFuncSetAttribute(gemm_half<1>, cudaFuncAttributeMaxDynamicSharedMemorySize, SMEM_DYN);
    cudaFuncSetAttribute(gemm_half<2>, cudaFuncAttributeMaxDynamicSharedMemorySize, SMEM_DYN);

    tsplit_deg_kernel<<<dim3(16, 16, BATCH), 256>>>(ind);
    combo_kernel<<<2468, 256>>>(conv_w);
    xs_half_kernel<<<8192, 256>>>(x);
    gemm_half<1><<<dim3(8, 2, BATCH), 512, SMEM_DYN>>>(nullptr);
    gemm_half<2><<<dim3(8, 2, BATCH), 512, SMEM_DYN>>>(conv_b);
    apply_kernel<<<2048, 256>>>(out, gamma, beta);
}